// round 13
// baseline (speedup 1.0000x reference)
#include <cuda_runtime.h>
#include <cuda_bf16.h>
#include <cstddef>

#define BATCH 8
#define CDIM  64
#define HDIM  256
#define WDIM  256
#define WH    65536
#define CWH   (CDIM*WH)

// -------------------- scratch --------------------
__device__ float g_q [BATCH * CWH];
__device__ float g_k [BATCH * CWH];
__device__ float g_v [BATCH * CWH];
__device__ float g_qm[BATCH * CWH];
__device__ float g_part1[BATCH * 64 * 4096];
__device__ float g_part2[BATCH * 64 * 4096];
__device__ float g_R1[BATCH * 4096];
__device__ float g_R2[BATCH * 4096];
__device__ float g_M[BATCH * 4096];

__device__ __forceinline__ float* out_buf(int id) {
    return id == 0 ? g_q : id == 1 ? g_k : id == 2 ? g_v : g_qm;
}

// -------------------- f32x2 helpers --------------------
typedef unsigned long long u64t;
__device__ __forceinline__ u64t pk2(float lo, float hi) {
    u64t r; asm("mov.b64 %0, {%1,%2};" : "=l"(r) : "f"(lo), "f"(hi)); return r;
}
__device__ __forceinline__ void unpk(u64t a, float& x, float& y) {
    asm("mov.b64 {%0,%1}, %2;" : "=f"(x), "=f"(y) : "l"(a));
}
__device__ __forceinline__ u64t fma2(u64t a, u64t b, u64t c) {
    u64t d; asm("fma.rn.f32x2 %0, %1, %2, %3;" : "=l"(d) : "l"(a), "l"(b), "l"(c)); return d;
}
__device__ __forceinline__ u64t add2(u64t a, u64t b) {
    u64t d; asm("add.rn.f32x2 %0, %1, %2;" : "=l"(d) : "l"(a), "l"(b)); return d;
}

// -------------------- cp.async helpers --------------------
__device__ __forceinline__ void cp16(void* s, const void* g) {
    unsigned sa = (unsigned)__cvta_generic_to_shared(s);
    asm volatile("cp.async.cg.shared.global [%0], [%1], 16;\n" :: "r"(sa), "l"(g));
}
// 4-byte copy with zero-fill predicate (src_size = 0 -> writes 0.0f)
__device__ __forceinline__ void cp4z(void* s, const void* g, int src_size) {
    unsigned sa = (unsigned)__cvta_generic_to_shared(s);
    asm volatile("cp.async.ca.shared.global [%0], [%1], 4, %2;\n"
                 :: "r"(sa), "l"(g), "r"(src_size));
}
__device__ __forceinline__ void cp_commit() { asm volatile("cp.async.commit_group;\n"); }
template<int N> __device__ __forceinline__ void cp_wait() {
    asm volatile("cp.async.wait_group %0;\n" :: "n"(N));
}

// -------------------- fused DSC: 5 phases per block, one launch (R9 + async tiles)
// Phases: 0:q(x)  1:k(x)  2:v(x)[acc init]  3:v(avg)[acc cont, store]  4:qm(mask)

#define DSC_SMEM_FLOATS (11520 + 8192 + 8192 + 576 + 64 + 64)

__global__ __launch_bounds__(256, 2)
void dsc5_kernel(const float* __restrict__ x, const float* __restrict__ mask,
                 const float* __restrict__ avg,
                 const float* __restrict__ dwq, const float* __restrict__ dbq,
                 const float* __restrict__ pwqW, const float* __restrict__ pbq,
                 const float* __restrict__ dwk, const float* __restrict__ dbk,
                 const float* __restrict__ pwkW, const float* __restrict__ pbk,
                 const float* __restrict__ dwv, const float* __restrict__ dbv,
                 const float* __restrict__ pwvW, const float* __restrict__ pbv)
{
    extern __shared__ float sm[];
    float* xs    = sm;                 // 64 x 10 x 18
    float* dwout = xs + 11520;         // 64 x 128
    float* pwq   = dwout + 8192;       // 64 x 32 float4 (w,w,w',w')
    float* fsm   = pwq + 8192;         // 576
    float* dbsm  = fsm + 576;          // 64
    float* pbsm  = dbsm + 64;          // 64

    const int tid = threadIdx.x;
    const int b   = blockIdx.z;
    const int ty0 = blockIdx.y * 8;
    const int tx0 = blockIdx.x * 16;

    // async tile load: thread = (channel, quarter); 45 contiguous elements of
    // the 180-float channel tile; cp.async.ca 4B with src_size=0 zero-fill
    // for SAME padding. No register round-trip, no LDG->STS scoreboard stall.
    const int lc = tid >> 2;           // channel 0..63
    const int lq = tid & 3;            // quarter 0..3
    auto load_tile_async = [&](const float* __restrict__ inb) {
        const float* src = inb + lc * WH;
        float* dstc = xs + lc * 180;
        int r0 = lq * 45;
        int row = r0 / 18, col = r0 % 18;   // constant-foldable per lq
        for (int j = 0; j < 45; j++) {
            int yy = ty0 - 1 + row;
            int xx = tx0 - 1 + col;
            bool ok = (yy >= 0 && yy < HDIM && xx >= 0 && xx < WDIM);
            const float* g = src + (ok ? (yy * WDIM + xx) : 0);
            cp4z(dstc + row * 18 + col, g, ok ? 4 : 0);
            col++; if (col == 18) { col = 0; row++; }
        }
        cp_commit();
    };

    // exposed load: only the x tile (async, waited at ph0 top)
    load_tile_async(x + (size_t)b * CWH);

    const float* DW[5] = { dwq, dwk, dwv, dwv, dwq };
    const float* DB[5] = { dbq, dbk, dbv, dbv, dbq };
    const float* PW[5] = { pwqW, pwkW, pwvW, pwvW, pwqW };
    const float* PB[5] = { pbq, pbk, pbv, pbv, pbq };
    const int    OID[5] = { 0, 1, 2, 2, 3 };

    const int dp   = tid & 63;
    const int cg   = tid >> 6;           // 0..3
    const int drow = (2 * dp) >> 4;
    const int dcol = (2 * dp) & 15;
    const int pp0 = tid & 31;
    const int og  = tid >> 5;            // 0..7

    u64t acc[8][2];

#pragma unroll
    for (int ph = 0; ph < 5; ph++) {
        cp_wait<0>();      // tile copy for this phase complete (thread-local)
        __syncthreads();   // all threads' copies visible; prev pw done with smem

        if (ph != 3) {
            for (int i = tid; i < 576; i += 256) fsm[i] = DW[ph][i];
            for (int idx = tid; idx < 2048; idx += 256) {
                int o = idx >> 5, cc = idx & 31;
                float w0 = PW[ph][o * 64 + 2 * cc];
                float w1 = PW[ph][o * 64 + 2 * cc + 1];
                ((float4*)pwq)[idx] = make_float4(w0, w0, w1, w1);
            }
            if (tid < 64) { dbsm[tid] = DB[ph][tid]; pbsm[tid] = PB[ph][tid]; }
            __syncthreads();
        }

        // depthwise 3x3 + bias (R9 verbatim)
        for (int c = cg; c < 64; c += 4) {
            const float* base = xs + c * 180 + drow * 18 + dcol;
            float r[3][4];
#pragma unroll
            for (int dy = 0; dy < 3; dy++) {
                float2 a  = *(const float2*)(base + dy * 18);
                float2 b2 = *(const float2*)(base + dy * 18 + 2);
                r[dy][0] = a.x; r[dy][1] = a.y; r[dy][2] = b2.x; r[dy][3] = b2.y;
            }
            const float* w = fsm + c * 9;
            float s0 = dbsm[c], s1 = s0;
#pragma unroll
            for (int dy = 0; dy < 3; dy++) {
                s0 += w[3*dy] * r[dy][0] + w[3*dy+1] * r[dy][1] + w[3*dy+2] * r[dy][2];
                s1 += w[3*dy] * r[dy][1] + w[3*dy+1] * r[dy][2] + w[3*dy+2] * r[dy][3];
            }
            *(float2*)&dwout[c * 128 + 2 * dp] = make_float2(s0, s1);
        }
        __syncthreads();   // dw done: dwout ready, xs free for next tile

        if (ph != 3) {
            float scale = (ph == 2) ? 2.0f : 1.0f;
#pragma unroll
            for (int i = 0; i < 8; i++) {
                float pbv2 = pbsm[og * 8 + i] * scale;
                acc[i][0] = pk2(pbv2, pbv2);
                acc[i][1] = acc[i][0];
            }
        }

        // async prefetch of next phase's tile (fire-and-forget behind pw)
        if (ph == 2)      load_tile_async(avg  + (size_t)b * CWH);
        else if (ph == 3) load_tile_async(mask + (size_t)b * CWH);

        // pointwise 64x64 FFMA2 (R9 verbatim)
        for (int cc = 0; cc < 32; cc++) {
            int c2 = 2 * cc;
            u64t dA0 = *(const u64t*)&dwout[c2 * 128 + 2 * pp0];
            u64t dA1 = *(const u64t*)&dwout[c2 * 128 + 64 + 2 * pp0];
            u64t dB0 = *(const u64t*)&dwout[(c2 + 1) * 128 + 2 * pp0];
            u64t dB1 = *(const u64t*)&dwout[(c2 + 1) * 128 + 64 + 2 * pp0];
#pragma unroll
            for (int i = 0; i < 8; i++) {
                ulonglong2 w2 = *(const ulonglong2*)&pwq[((og * 8 + i) * 32 + cc) * 4];
                acc[i][0] = fma2(w2.x, dA0, acc[i][0]);
                acc[i][1] = fma2(w2.x, dA1, acc[i][1]);
                acc[i][0] = fma2(w2.y, dB0, acc[i][0]);
                acc[i][1] = fma2(w2.y, dB1, acc[i][1]);
            }
        }

        if (ph != 2) {
            float* outp = out_buf(OID[ph]) + (size_t)b * CWH;
            const int q0 = 2 * pp0;
            const int gy0 = ty0 + (q0 >> 4), gx0 = tx0 + (q0 & 15);
            const size_t base0 = (size_t)gy0 * WDIM + gx0;
#pragma unroll
            for (int i = 0; i < 8; i++) {
                int o = og * 8 + i;
                size_t gi0 = (size_t)o * WH + base0;
                size_t gi1 = gi0 + 4 * WDIM;
                *(u64t*)&outp[gi0] = acc[i][0];
                *(u64t*)&outp[gi1] = acc[i][1];
            }
        }
    }
}

// -------------------- QK (R9, verbatim 4i x 4j) --------------------
#define QSTR 36
#define KSTR 68

__global__ __launch_bounds__(256)
void qk_kernel()
{
    const int b = blockIdx.y;
    const int chunk = blockIdx.x;
    const int p0 = chunk * 1024;
    const int tid = threadIdx.x;
    const int ti = tid >> 4, tj = tid & 15;
    const int i0 = ti * 4, j0 = tj * 4;

    __shared__ __align__(16) float q1s[2][64 * QSTR];
    __shared__ __align__(16) float q2s[2][64 * QSTR];
    __shared__ __align__(16) float ks [2][32 * KSTR];

    const float* qb  = g_q  + (size_t)b * CWH;
    const float* qmb = g_qm + (size_t)b * CWH;
    const float* kb  = g_k  + (size_t)b * CWH;

    auto prefetch = [&](int kt, int s) {
        const int pp2 = p0 + kt * 32;
        for (int e = tid; e < 512; e += 256) {
            int i = e >> 3, u4 = (e & 7) * 4;
            cp16(&q1s[s][i * QSTR + u4], qb  + (size_t)i * WH + pp2 + u4);
            cp16(&q2s[s][i * QSTR + u4], qmb + (size_t)i * WH + pp2 + u4);
        }
        for (int e = tid; e < 512; e += 256) {
            int u = e >> 4, j4 = (e & 15) * 4;
            cp16(&ks[s][u * KSTR + j4], kb + (size_t)(pp2 + u) * 64 + j4);
        }
        cp_commit();
    };

    u64t acc1[4][2] = {};
    u64t acc2[4][2] = {};

    prefetch(0, 0);
    prefetch(1, 1);

    for (int kt = 0; kt < 32; kt++) {
        if (kt == 31) cp_wait<0>(); else cp_wait<1>();
        __syncthreads();
        const int cur = kt & 1;
#pragma unroll 2
        for (int u = 0; u < 32; u++) {
            ulonglong2 bv = *(const ulonglong2*)&ks[cur][u * KSTR + j0];
#pragma unroll
            for (int r = 0; r < 4; r++) {
                float av1 = q1s[cur][(i0 + r) * QSTR + u];
                u64t a1d = pk2(av1, av1);
                acc1[r][0] = fma2(a1d, bv.x, acc1[r][0]);
                acc1[r][1] = fma2(a1d, bv.y, acc1[r][1]);
                float av2 = q2s[cur][(i0 + r) * QSTR + u];
                u64t a2d = pk2(av2, av2);
                acc2[r][0] = fma2(a2d, bv.x, acc2[r][0]);
                acc2[r][1] = fma2(a2d, bv.y, acc2[r][1]);
            }
        }
        __syncthreads();
        if (kt + 2 < 32) prefetch(kt + 2, cur);
    }

    float* P1 = g_part1 + ((size_t)b * 64 + chunk) * 4096;
    float* P2 = g_part2 + ((size_t)b * 64 + chunk) * 4096;
#pragma unroll
    for (int r = 0; r < 4; r++) {
        float a, bb, c, d;
        unpk(acc1[r][0], a, bb); unpk(acc1[r][1], c, d);
        *(float4*)&P1[(i0 + r) * 64 + j0] = make_float4(a, bb, c, d);
        unpk(acc2[r][0], a, bb); unpk(acc2[r][1], c, d);
        *(float4*)&P2[(i0 + r) * 64 + j0] = make_float4(a, bb, c, d);
    }
}

// -------------------- parallel partial reduce (verbatim) --------------------
__global__ __launch_bounds__(512)
void reduce_kernel()
{
    const int b = blockIdx.y;
    const int e = blockIdx.x * 512 + threadIdx.x;
    const float* P1 = g_part1 + (size_t)b * 64 * 4096;
    const float* P2 = g_part2 + (size_t)b * 64 * 4096;
    float s1 = 0.0f, s2 = 0.0f;
#pragma unroll 8
    for (int ch = 0; ch < 64; ch++) {
        s1 += P1[(size_t)ch * 4096 + e];
        s2 += P2[(size_t)ch * 4096 + e];
    }
    g_R1[(size_t)b * 4096 + e] = s1 * (1.0f / 256.0f);
    g_R2[(size_t)b * 4096 + e] = s2 * (1.0f / 256.0f);
}

// -------------------- softmax(flat 4096) x2 + M = A1+A2 (verbatim) ----------
__global__ __launch_bounds__(256)
void softmax_kernel()
{
    __shared__ float buf[4096];
    __shared__ float red[256];
    const int b = blockIdx.x;
    const int tid = threadIdx.x;

    for (int m = 0; m < 2; m++) {
        const float* R = (m == 0 ? g_R1 : g_R2) + (size_t)b * 4096;
        __syncthreads();
        float lmax = -1e30f;
        for (int e = tid; e < 4096; e += 256) {
            float s = R[e];
            buf[e] = s;
            lmax = fmaxf(lmax, s);
        }
        red[tid] = lmax; __syncthreads();
        for (int s = 128; s; s >>= 1) {
            if (tid < s) red[tid] = fmaxf(red[tid], red[tid + s]);
            __syncthreads();
        }
        float mx = red[0];
        __syncthreads();

        float lsum = 0.0f;
        for (int e = tid; e < 4096; e += 256) {
            float ev = __expf(buf[e] - mx);
            buf[e] = ev;
            lsum += ev;
        }
        red[tid] = lsum; __syncthreads();
        for (int s = 128; s; s >>= 1) {
            if (tid < s) red[tid] += red[tid + s];
            __syncthreads();
        }
        float inv = 1.0f / red[0];

        for (int e = tid; e < 4096; e += 256) {
            float val = buf[e] * inv;
            float* mp = g_M + (size_t)b * 4096 + e;
            if (m == 0) *mp = val;
            else        *mp += val;
        }
    }
}

// -------------------- out = M @ v_sum + x (verbatim) --------------------
#define OUT_SMEM_FLOATS (8192 + 2 * 8192)

__global__ __launch_bounds__(512)
void out_kernel(const float* __restrict__ x, float* __restrict__ out)
{
    extern __shared__ float osm[];
    float* mq = osm;
    float* vt = osm + 8192;

    const int b  = blockIdx.y;
    const int p0 = blockIdx.x * 512;
    const int tid = threadIdx.x;
    const int pp = tid & 63, og = tid >> 6;

    for (int idx = tid; idx < 2048; idx += 512) {
        int o = idx >> 5, cc = idx & 31;
        float m0 = g_M[(size_t)b * 4096 + o * 64 + 2 * cc];
        float m1 = g_M[(size_t)b * 4096 + o * 64 + 2 * cc + 1];
        ((float4*)mq)[idx] = make_float4(m0, m0, m1, m1);
    }

    const float* vb = g_v + (size_t)b * CWH + p0;

    auto prefetch = [&](int s, int buf) {
        const float* src = vb + s * 128;
        float* dst = vt + buf * 8192;
        for (int e = tid; e < 2048; e += 512) {
            int c = e >> 5, q4 = (e & 31) * 4;
            cp16(&dst[c * 128 + q4], src + (size_t)c * WH + q4);
        }
        cp_commit();
    };

    prefetch(0, 0);
    prefetch(1, 1);

    const float* xb = x + (size_t)b * CWH + p0 + 2 * pp;
    float* ob = out + (size_t)b * CWH + p0 + 2 * pp;

    for (int s = 0; s < 4; s++) {
        if (s == 3) cp_wait<0>(); else cp_wait<1>();
        __syncthreads();
        const float* cvt = vt + (s & 1) * 8192;

        u64t xr[8];
#pragma unroll
        for (int i = 0; i < 8; i++) {
            int o = og * 8 + i;
            xr[i] = *(const u64t*)(xb + (size_t)o * WH + s * 128);
        }

        u64t acc[8] = {};
#pragma unroll 4
        for (int cc = 0; cc < 32; cc++) {
            u64t d0 = *(const u64t*)&cvt[(2 * cc) * 128 + 2 * pp];
            u64t d1 = *(const u64t*)&cvt[(2 * cc + 1) * 128 + 2 * pp];
#pragma unroll
            for (int i = 0; i < 8; i++) {
                ulonglong2 w2 = *(const ulonglong2*)&mq[((og * 8 + i) * 32 + cc) * 4];
                acc[i] = fma2(w2.x, d0, acc[i]);
                acc[i] = fma2(w2.y, d1, acc[i]);
            }
        }

#pragma unroll
        for (int i = 0; i < 8; i++) {
            int o = og * 8 + i;
            *(u64t*)(ob + (size_t)o * WH + s * 128) = add2(acc[i], xr[i]);
        }

        __syncthreads();
        if (s + 2 < 4) prefetch(s + 2, s & 1);
    }
}

// -------------------- launch --------------------
extern "C" void kernel_launch(void* const* d_in, const int* in_sizes, int n_in,
                              void* d_out, int out_size)
{
    const float* x    = (const float*)d_in[0];
    const float* mask = (const float*)d_in[1];
    const float* avg  = (const float*)d_in[2];
    const float* dwq = (const float*)d_in[3];
    const float* dbq = (const float*)d_in[4];
    const float* pwq = (const float*)d_in[5];
    const float* pbq = (const float*)d_in[6];
    const float* dwk = (const float*)d_in[7];
    const float* dbk = (const float*)d_in[8];
    const float* pwk = (const float*)d_in[9];
    const float* pbk = (const float*)d_in[10];
    const float* dwv = (const float*)d_in[11];
    const float* dbv = (const float*)d_in[12];
    const float* pwv = (const float*)d_in[13];
    const float* pbv = (const float*)d_in[14];
    float* out = (float*)d_out;

    const size_t dsc_smem = DSC_SMEM_FLOATS * sizeof(float);
    cudaFuncSetAttribute(dsc5_kernel, cudaFuncAttributeMaxDynamicSharedMemorySize, (int)dsc_smem);
    const size_t out_smem = OUT_SMEM_FLOATS * sizeof(float);
    cudaFuncSetAttribute(out_kernel, cudaFuncAttributeMaxDynamicSharedMemorySize, (int)out_smem);

    dsc5_kernel<<<dim3(WDIM / 16, HDIM / 8, BATCH), 256, dsc_smem>>>(
        x, mask, avg,
        dwq, dbq, pwq, pbq,
        dwk, dbk, pwk, pbk,
        dwv, dbv, pwv, pbv);

    qk_kernel<<<dim3(64, BATCH), 256>>>();
    reduce_kernel<<<dim3(8, BATCH), 512>>>();
    softmax_kernel<<<BATCH, 256>>>();
    out_kernel<<<dim3(WH / 512, BATCH), 512, out_smem>>>(x, out);
}

// round 14
// speedup vs baseline: 1.1998x; 1.1998x over previous
#include <cuda_runtime.h>
#include <cuda_bf16.h>
#include <cstddef>

#define BATCH 8
#define CDIM  64
#define HDIM  256
#define WDIM  256
#define WH    65536
#define CWH   (CDIM*WH)

// -------------------- scratch --------------------
__device__ float g_q [BATCH * CWH];
__device__ float g_k [BATCH * CWH];
__device__ float g_v [BATCH * CWH];
__device__ float g_qm[BATCH * CWH];
__device__ float g_part1[BATCH * 64 * 4096];
__device__ float g_part2[BATCH * 64 * 4096];
__device__ float g_R1[BATCH * 4096];
__device__ float g_R2[BATCH * 4096];
__device__ float g_M[BATCH * 4096];

__device__ __forceinline__ float* out_buf(int id) {
    return id == 0 ? g_q : id == 1 ? g_k : id == 2 ? g_v : g_qm;
}

// -------------------- f32x2 helpers --------------------
typedef unsigned long long u64t;
__device__ __forceinline__ u64t pk2(float lo, float hi) {
    u64t r; asm("mov.b64 %0, {%1,%2};" : "=l"(r) : "f"(lo), "f"(hi)); return r;
}
__device__ __forceinline__ void unpk(u64t a, float& x, float& y) {
    asm("mov.b64 {%0,%1}, %2;" : "=f"(x), "=f"(y) : "l"(a));
}
__device__ __forceinline__ u64t fma2(u64t a, u64t b, u64t c) {
    u64t d; asm("fma.rn.f32x2 %0, %1, %2, %3;" : "=l"(d) : "l"(a), "l"(b), "l"(c)); return d;
}
__device__ __forceinline__ u64t add2(u64t a, u64t b) {
    u64t d; asm("add.rn.f32x2 %0, %1, %2;" : "=l"(d) : "l"(a), "l"(b)); return d;
}

// -------------------- cp.async helpers --------------------
__device__ __forceinline__ void cp16(void* s, const void* g) {
    unsigned sa = (unsigned)__cvta_generic_to_shared(s);
    asm volatile("cp.async.cg.shared.global [%0], [%1], 16;\n" :: "r"(sa), "l"(g));
}
__device__ __forceinline__ void cp_commit() { asm volatile("cp.async.commit_group;\n"); }
template<int N> __device__ __forceinline__ void cp_wait() {
    asm volatile("cp.async.wait_group %0;\n" :: "n"(N));
}

// -------------------- fused DSC: 5 phases per block, one launch (R9, verbatim) --
// Phases: 0:q(x)  1:k(x)  2:v(x)[acc init]  3:v(avg)[acc cont, store]  4:qm(mask)

#define DSC_SMEM_FLOATS (11520 + 8192 + 8192 + 576 + 64 + 64)

__global__ __launch_bounds__(256, 2)
void dsc5_kernel(const float* __restrict__ x, const float* __restrict__ mask,
                 const float* __restrict__ avg,
                 const float* __restrict__ dwq, const float* __restrict__ dbq,
                 const float* __restrict__ pwqW, const float* __restrict__ pbq,
                 const float* __restrict__ dwk, const float* __restrict__ dbk,
                 const float* __restrict__ pwkW, const float* __restrict__ pbk,
                 const float* __restrict__ dwv, const float* __restrict__ dbv,
                 const float* __restrict__ pwvW, const float* __restrict__ pbv)
{
    extern __shared__ float sm[];
    float* xs    = sm;                 // 64 x 10 x 18
    float* dwout = xs + 11520;         // 64 x 128
    float* pwq   = dwout + 8192;       // 64 x 32 float4 (w,w,w',w')
    float* fsm   = pwq + 8192;         // 576
    float* dbsm  = fsm + 576;          // 64
    float* pbsm  = dbsm + 64;          // 64

    const int tid = threadIdx.x;
    const int b   = blockIdx.z;
    const int ty0 = blockIdx.y * 8;
    const int tx0 = blockIdx.x * 16;

    auto load_tile = [&](const float* __restrict__ inb) {
        for (int idx = tid; idx < 11520; idx += 256) {
            int c = idx / 180, r = idx % 180;
            int yy = r / 18 - 1 + ty0;
            int xx = r % 18 - 1 + tx0;
            float v = 0.0f;
            if (yy >= 0 && yy < HDIM && xx >= 0 && xx < WDIM)
                v = inb[c * WH + yy * WDIM + xx];
            xs[idx] = v;
        }
    };

    // exposed load: only the x tile
    load_tile(x + (size_t)b * CWH);

    const float* DW[5] = { dwq, dwk, dwv, dwv, dwq };
    const float* DB[5] = { dbq, dbk, dbv, dbv, dbq };
    const float* PW[5] = { pwqW, pwkW, pwvW, pwvW, pwqW };
    const float* PB[5] = { pbq, pbk, pbv, pbv, pbq };
    const int    OID[5] = { 0, 1, 2, 2, 3 };

    const int dp   = tid & 63;
    const int cg   = tid >> 6;           // 0..3
    const int drow = (2 * dp) >> 4;
    const int dcol = (2 * dp) & 15;
    const int pp0 = tid & 31;
    const int og  = tid >> 5;            // 0..7

    u64t acc[8][2];

#pragma unroll
    for (int ph = 0; ph < 5; ph++) {
        __syncthreads();

        if (ph != 3) {
            for (int i = tid; i < 576; i += 256) fsm[i] = DW[ph][i];
            for (int idx = tid; idx < 2048; idx += 256) {
                int o = idx >> 5, cc = idx & 31;
                float w0 = PW[ph][o * 64 + 2 * cc];
                float w1 = PW[ph][o * 64 + 2 * cc + 1];
                ((float4*)pwq)[idx] = make_float4(w0, w0, w1, w1);
            }
            if (tid < 64) { dbsm[tid] = DB[ph][tid]; pbsm[tid] = PB[ph][tid]; }
            __syncthreads();
        }

        // depthwise 3x3 + bias (R9 verbatim)
        for (int c = cg; c < 64; c += 4) {
            const float* base = xs + c * 180 + drow * 18 + dcol;
            float r[3][4];
#pragma unroll
            for (int dy = 0; dy < 3; dy++) {
                float2 a  = *(const float2*)(base + dy * 18);
                float2 b2 = *(const float2*)(base + dy * 18 + 2);
                r[dy][0] = a.x; r[dy][1] = a.y; r[dy][2] = b2.x; r[dy][3] = b2.y;
            }
            const float* w = fsm + c * 9;
            float s0 = dbsm[c], s1 = s0;
#pragma unroll
            for (int dy = 0; dy < 3; dy++) {
                s0 += w[3*dy] * r[dy][0] + w[3*dy+1] * r[dy][1] + w[3*dy+2] * r[dy][2];
                s1 += w[3*dy] * r[dy][1] + w[3*dy+1] * r[dy][2] + w[3*dy+2] * r[dy][3];
            }
            *(float2*)&dwout[c * 128 + 2 * dp] = make_float2(s0, s1);
        }
        __syncthreads();   // dw done: dwout ready, xs free for next tile

        if (ph != 3) {
            float scale = (ph == 2) ? 2.0f : 1.0f;
#pragma unroll
            for (int i = 0; i < 8; i++) {
                float pbv2 = pbsm[og * 8 + i] * scale;
                acc[i][0] = pk2(pbv2, pbv2);
                acc[i][1] = acc[i][0];
            }
        }

        // prefetch next phase's tile into xs (hidden behind pw)
        if (ph == 2)      load_tile(avg  + (size_t)b * CWH);
        else if (ph == 3) load_tile(mask + (size_t)b * CWH);

        // pointwise 64x64 FFMA2 (R9 verbatim)
        for (int cc = 0; cc < 32; cc++) {
            int c2 = 2 * cc;
            u64t dA0 = *(const u64t*)&dwout[c2 * 128 + 2 * pp0];
            u64t dA1 = *(const u64t*)&dwout[c2 * 128 + 64 + 2 * pp0];
            u64t dB0 = *(const u64t*)&dwout[(c2 + 1) * 128 + 2 * pp0];
            u64t dB1 = *(const u64t*)&dwout[(c2 + 1) * 128 + 64 + 2 * pp0];
#pragma unroll
            for (int i = 0; i < 8; i++) {
                ulonglong2 w2 = *(const ulonglong2*)&pwq[((og * 8 + i) * 32 + cc) * 4];
                acc[i][0] = fma2(w2.x, dA0, acc[i][0]);
                acc[i][1] = fma2(w2.x, dA1, acc[i][1]);
                acc[i][0] = fma2(w2.y, dB0, acc[i][0]);
                acc[i][1] = fma2(w2.y, dB1, acc[i][1]);
            }
        }

        if (ph != 2) {
            float* outp = out_buf(OID[ph]) + (size_t)b * CWH;
            const int q0 = 2 * pp0;
            const int gy0 = ty0 + (q0 >> 4), gx0 = tx0 + (q0 & 15);
            const size_t base0 = (size_t)gy0 * WDIM + gx0;
#pragma unroll
            for (int i = 0; i < 8; i++) {
                int o = og * 8 + i;
                size_t gi0 = (size_t)o * WH + base0;
                size_t gi1 = gi0 + 4 * WDIM;
                *(u64t*)&outp[gi0] = acc[i][0];
                *(u64t*)&outp[gi1] = acc[i][1];
            }
        }
    }
}

// -------------------- QK (R9 body; occupancy raised to 4 blocks/SM) ------------
#define QSTR 36
#define KSTR 68

__global__ __launch_bounds__(256, 4)
void qk_kernel()
{
    const int b = blockIdx.y;
    const int chunk = blockIdx.x;
    const int p0 = chunk * 1024;
    const int tid = threadIdx.x;
    const int ti = tid >> 4, tj = tid & 15;
    const int i0 = ti * 4, j0 = tj * 4;

    __shared__ __align__(16) float q1s[2][64 * QSTR];
    __shared__ __align__(16) float q2s[2][64 * QSTR];
    __shared__ __align__(16) float ks [2][32 * KSTR];

    const float* qb  = g_q  + (size_t)b * CWH;
    const float* qmb = g_qm + (size_t)b * CWH;
    const float* kb  = g_k  + (size_t)b * CWH;

    auto prefetch = [&](int kt, int s) {
        const int pp2 = p0 + kt * 32;
        for (int e = tid; e < 512; e += 256) {
            int i = e >> 3, u4 = (e & 7) * 4;
            cp16(&q1s[s][i * QSTR + u4], qb  + (size_t)i * WH + pp2 + u4);
            cp16(&q2s[s][i * QSTR + u4], qmb + (size_t)i * WH + pp2 + u4);
        }
        for (int e = tid; e < 512; e += 256) {
            int u = e >> 4, j4 = (e & 15) * 4;
            cp16(&ks[s][u * KSTR + j4], kb + (size_t)(pp2 + u) * 64 + j4);
        }
        cp_commit();
    };

    u64t acc1[4][2] = {};
    u64t acc2[4][2] = {};

    prefetch(0, 0);
    prefetch(1, 1);

    for (int kt = 0; kt < 32; kt++) {
        if (kt == 31) cp_wait<0>(); else cp_wait<1>();
        __syncthreads();
        const int cur = kt & 1;
#pragma unroll 2
        for (int u = 0; u < 32; u++) {
            ulonglong2 bv = *(const ulonglong2*)&ks[cur][u * KSTR + j0];
#pragma unroll
            for (int r = 0; r < 4; r++) {
                float av1 = q1s[cur][(i0 + r) * QSTR + u];
                u64t a1d = pk2(av1, av1);
                acc1[r][0] = fma2(a1d, bv.x, acc1[r][0]);
                acc1[r][1] = fma2(a1d, bv.y, acc1[r][1]);
                float av2 = q2s[cur][(i0 + r) * QSTR + u];
                u64t a2d = pk2(av2, av2);
                acc2[r][0] = fma2(a2d, bv.x, acc2[r][0]);
                acc2[r][1] = fma2(a2d, bv.y, acc2[r][1]);
            }
        }
        __syncthreads();
        if (kt + 2 < 32) prefetch(kt + 2, cur);
    }

    float* P1 = g_part1 + ((size_t)b * 64 + chunk) * 4096;
    float* P2 = g_part2 + ((size_t)b * 64 + chunk) * 4096;
#pragma unroll
    for (int r = 0; r < 4; r++) {
        float a, bb, c, d;
        unpk(acc1[r][0], a, bb); unpk(acc1[r][1], c, d);
        *(float4*)&P1[(i0 + r) * 64 + j0] = make_float4(a, bb, c, d);
        unpk(acc2[r][0], a, bb); unpk(acc2[r][1], c, d);
        *(float4*)&P2[(i0 + r) * 64 + j0] = make_float4(a, bb, c, d);
    }
}

// -------------------- parallel partial reduce (verbatim) --------------------
__global__ __launch_bounds__(512)
void reduce_kernel()
{
    const int b = blockIdx.y;
    const int e = blockIdx.x * 512 + threadIdx.x;
    const float* P1 = g_part1 + (size_t)b * 64 * 4096;
    const float* P2 = g_part2 + (size_t)b * 64 * 4096;
    float s1 = 0.0f, s2 = 0.0f;
#pragma unroll 8
    for (int ch = 0; ch < 64; ch++) {
        s1 += P1[(size_t)ch * 4096 + e];
        s2 += P2[(size_t)ch * 4096 + e];
    }
    g_R1[(size_t)b * 4096 + e] = s1 * (1.0f / 256.0f);
    g_R2[(size_t)b * 4096 + e] = s2 * (1.0f / 256.0f);
}

// -------------------- softmax(flat 4096) x2 + M = A1+A2 (verbatim) ----------
__global__ __launch_bounds__(256)
void softmax_kernel()
{
    __shared__ float buf[4096];
    __shared__ float red[256];
    const int b = blockIdx.x;
    const int tid = threadIdx.x;

    for (int m = 0; m < 2; m++) {
        const float* R = (m == 0 ? g_R1 : g_R2) + (size_t)b * 4096;
        __syncthreads();
        float lmax = -1e30f;
        for (int e = tid; e < 4096; e += 256) {
            float s = R[e];
            buf[e] = s;
            lmax = fmaxf(lmax, s);
        }
        red[tid] = lmax; __syncthreads();
        for (int s = 128; s; s >>= 1) {
            if (tid < s) red[tid] = fmaxf(red[tid], red[tid + s]);
            __syncthreads();
        }
        float mx = red[0];
        __syncthreads();

        float lsum = 0.0f;
        for (int e = tid; e < 4096; e += 256) {
            float ev = __expf(buf[e] - mx);
            buf[e] = ev;
            lsum += ev;
        }
        red[tid] = lsum; __syncthreads();
        for (int s = 128; s; s >>= 1) {
            if (tid < s) red[tid] += red[tid + s];
            __syncthreads();
        }
        float inv = 1.0f / red[0];

        for (int e = tid; e < 4096; e += 256) {
            float val = buf[e] * inv;
            float* mp = g_M + (size_t)b * 4096 + e;
            if (m == 0) *mp = val;
            else        *mp += val;
        }
    }
}

// -------------------- out = M @ v_sum + x (verbatim) --------------------
#define OUT_SMEM_FLOATS (8192 + 2 * 8192)

__global__ __launch_bounds__(512)
void out_kernel(const float* __restrict__ x, float* __restrict__ out)
{
    extern __shared__ float osm[];
    float* mq = osm;
    float* vt = osm + 8192;

    const int b  = blockIdx.y;
    const int p0 = blockIdx.x * 512;
    const int tid = threadIdx.x;
    const int pp = tid & 63, og = tid >> 6;

    for (int idx = tid; idx < 2048; idx += 512) {
        int o = idx >> 5, cc = idx & 31;
        float m0 = g_M[(size_t)b * 4096 + o * 64 + 2 * cc];
        float m1 = g_M[(size_t)b * 4096 + o * 64 + 2 * cc + 1];
        ((float4*)mq)[idx] = make_float4(m0, m0, m1, m1);
    }

    const float* vb = g_v + (size_t)b * CWH + p0;

    auto prefetch = [&](int s, int buf) {
        const float* src = vb + s * 128;
        float* dst = vt + buf * 8192;
        for (int e = tid; e < 2048; e += 512) {
            int c = e >> 5, q4 = (e & 31) * 4;
            cp16(&dst[c * 128 + q4], src + (size_t)c * WH + q4);
        }
        cp_commit();
    };

    prefetch(0, 0);
    prefetch(1, 1);

    const float* xb = x + (size_t)b * CWH + p0 + 2 * pp;
    float* ob = out + (size_t)b * CWH + p0 + 2 * pp;

    for (int s = 0; s < 4; s++) {
        if (s == 3) cp_wait<0>(); else cp_wait<1>();
        __syncthreads();
        const float* cvt = vt + (s & 1) * 8192;

        u64t xr[8];
#pragma unroll
        for (int i = 0; i < 8; i++) {
            int o = og * 8 + i;
            xr[i] = *(const u64t*)(xb + (size_t)o * WH + s * 128);
        }

        u64t acc[8] = {};
#pragma unroll 4
        for (int cc = 0; cc < 32; cc++) {
            u64t d0 = *(const u64t*)&cvt[(2 * cc) * 128 + 2 * pp];
            u64t d1 = *(const u64t*)&cvt[(2 * cc + 1) * 128 + 2 * pp];
#pragma unroll
            for (int i = 0; i < 8; i++) {
                ulonglong2 w2 = *(const ulonglong2*)&mq[((og * 8 + i) * 32 + cc) * 4];
                acc[i] = fma2(w2.x, d0, acc[i]);
                acc[i] = fma2(w2.y, d1, acc[i]);
            }
        }

#pragma unroll
        for (int i = 0; i < 8; i++) {
            int o = og * 8 + i;
            *(u64t*)(ob + (size_t)o * WH + s * 128) = add2(acc[i], xr[i]);
        }

        __syncthreads();
        if (s + 2 < 4) prefetch(s + 2, s & 1);
    }
}

// -------------------- launch --------------------
extern "C" void kernel_launch(void* const* d_in, const int* in_sizes, int n_in,
                              void* d_out, int out_size)
{
    const float* x    = (const float*)d_in[0];
    const float* mask = (const float*)d_in[1];
    const float* avg  = (const float*)d_in[2];
    const float* dwq = (const float*)d_in[3];
    const float* dbq = (const float*)d_in[4];
    const float* pwq = (const float*)d_in[5];
    const float* pbq = (const float*)d_in[6];
    const float* dwk = (const float*)d_in[7];
    const float* dbk = (const float*)d_in[8];
    const float* pwk = (const float*)d_in[9];
    const float* pbk = (const float*)d_in[10];
    const float* dwv = (const float*)d_in[11];
    const float* dbv = (const float*)d_in[12];
    const float* pwv = (const float*)d_in[13];
    const float* pbv = (const float*)d_in[14];
    float* out = (float*)d_out;

    const size_t dsc_smem = DSC_SMEM_FLOATS * sizeof(float);
    cudaFuncSetAttribute(dsc5_kernel, cudaFuncAttributeMaxDynamicSharedMemorySize, (int)dsc_smem);
    const size_t out_smem = OUT_SMEM_FLOATS * sizeof(float);
    cudaFuncSetAttribute(out_kernel, cudaFuncAttributeMaxDynamicSharedMemorySize, (int)out_smem);

    dsc5_kernel<<<dim3(WDIM / 16, HDIM / 8, BATCH), 256, dsc_smem>>>(
        x, mask, avg,
        dwq, dbq, pwq, pbq,
        dwk, dbk, pwk, pbk,
        dwv, dbv, pwv, pbv);

    qk_kernel<<<dim3(64, BATCH), 256>>>();
    reduce_kernel<<<dim3(8, BATCH), 512>>>();
    softmax_kernel<<<BATCH, 256>>>();
    out_kernel<<<dim3(WH / 512, BATCH), 512, out_smem>>>(x, out);
}

// round 15
// speedup vs baseline: 1.2471x; 1.0395x over previous
#include <cuda_runtime.h>
#include <cuda_bf16.h>
#include <cstddef>

#define BATCH 8
#define CDIM  64
#define HDIM  256
#define WDIM  256
#define WH    65536
#define CWH   (CDIM*WH)

#define NCHUNK 256          // qk p-chunks per batch (chunk = 256 = 8 k-tiles)
#define KT_PER_CHUNK 8

// -------------------- scratch --------------------
__device__ float g_q [BATCH * CWH];
__device__ float g_k [BATCH * CWH];
__device__ float g_v [BATCH * CWH];
__device__ float g_qm[BATCH * CWH];
__device__ float g_part1[BATCH * NCHUNK * 4096];
__device__ float g_part2[BATCH * NCHUNK * 4096];
__device__ float g_R1[BATCH * 4096];
__device__ float g_R2[BATCH * 4096];
__device__ float g_M[BATCH * 4096];

__device__ __forceinline__ float* out_buf(int id) {
    return id == 0 ? g_q : id == 1 ? g_k : id == 2 ? g_v : g_qm;
}

// -------------------- f32x2 helpers --------------------
typedef unsigned long long u64t;
__device__ __forceinline__ u64t pk2(float lo, float hi) {
    u64t r; asm("mov.b64 %0, {%1,%2};" : "=l"(r) : "f"(lo), "f"(hi)); return r;
}
__device__ __forceinline__ void unpk(u64t a, float& x, float& y) {
    asm("mov.b64 {%0,%1}, %2;" : "=f"(x), "=f"(y) : "l"(a));
}
__device__ __forceinline__ u64t fma2(u64t a, u64t b, u64t c) {
    u64t d; asm("fma.rn.f32x2 %0, %1, %2, %3;" : "=l"(d) : "l"(a), "l"(b), "l"(c)); return d;
}
__device__ __forceinline__ u64t add2(u64t a, u64t b) {
    u64t d; asm("add.rn.f32x2 %0, %1, %2;" : "=l"(d) : "l"(a), "l"(b)); return d;
}

// -------------------- cp.async helpers --------------------
__device__ __forceinline__ void cp16(void* s, const void* g) {
    unsigned sa = (unsigned)__cvta_generic_to_shared(s);
    asm volatile("cp.async.cg.shared.global [%0], [%1], 16;\n" :: "r"(sa), "l"(g));
}
__device__ __forceinline__ void cp_commit() { asm volatile("cp.async.commit_group;\n"); }
template<int N> __device__ __forceinline__ void cp_wait() {
    asm volatile("cp.async.wait_group %0;\n" :: "n"(N));
}

// -------------------- fused DSC: 5 phases per block, one launch (R9, verbatim) --
// Phases: 0:q(x)  1:k(x)  2:v(x)[acc init]  3:v(avg)[acc cont, store]  4:qm(mask)

#define DSC_SMEM_FLOATS (11520 + 8192 + 8192 + 576 + 64 + 64)

__global__ __launch_bounds__(256, 2)
void dsc5_kernel(const float* __restrict__ x, const float* __restrict__ mask,
                 const float* __restrict__ avg,
                 const float* __restrict__ dwq, const float* __restrict__ dbq,
                 const float* __restrict__ pwqW, const float* __restrict__ pbq,
                 const float* __restrict__ dwk, const float* __restrict__ dbk,
                 const float* __restrict__ pwkW, const float* __restrict__ pbk,
                 const float* __restrict__ dwv, const float* __restrict__ dbv,
                 const float* __restrict__ pwvW, const float* __restrict__ pbv)
{
    extern __shared__ float sm[];
    float* xs    = sm;                 // 64 x 10 x 18
    float* dwout = xs + 11520;         // 64 x 128
    float* pwq   = dwout + 8192;       // 64 x 32 float4 (w,w,w',w')
    float* fsm   = pwq + 8192;         // 576
    float* dbsm  = fsm + 576;          // 64
    float* pbsm  = dbsm + 64;          // 64

    const int tid = threadIdx.x;
    const int b   = blockIdx.z;
    const int ty0 = blockIdx.y * 8;
    const int tx0 = blockIdx.x * 16;

    auto load_tile = [&](const float* __restrict__ inb) {
        for (int idx = tid; idx < 11520; idx += 256) {
            int c = idx / 180, r = idx % 180;
            int yy = r / 18 - 1 + ty0;
            int xx = r % 18 - 1 + tx0;
            float v = 0.0f;
            if (yy >= 0 && yy < HDIM && xx >= 0 && xx < WDIM)
                v = inb[c * WH + yy * WDIM + xx];
            xs[idx] = v;
        }
    };

    // exposed load: only the x tile
    load_tile(x + (size_t)b * CWH);

    const float* DW[5] = { dwq, dwk, dwv, dwv, dwq };
    const float* DB[5] = { dbq, dbk, dbv, dbv, dbq };
    const float* PW[5] = { pwqW, pwkW, pwvW, pwvW, pwqW };
    const float* PB[5] = { pbq, pbk, pbv, pbv, pbq };
    const int    OID[5] = { 0, 1, 2, 2, 3 };

    const int dp   = tid & 63;
    const int cg   = tid >> 6;           // 0..3
    const int drow = (2 * dp) >> 4;
    const int dcol = (2 * dp) & 15;
    const int pp0 = tid & 31;
    const int og  = tid >> 5;            // 0..7

    u64t acc[8][2];

#pragma unroll
    for (int ph = 0; ph < 5; ph++) {
        __syncthreads();

        if (ph != 3) {
            for (int i = tid; i < 576; i += 256) fsm[i] = DW[ph][i];
            for (int idx = tid; idx < 2048; idx += 256) {
                int o = idx >> 5, cc = idx & 31;
                float w0 = PW[ph][o * 64 + 2 * cc];
                float w1 = PW[ph][o * 64 + 2 * cc + 1];
                ((float4*)pwq)[idx] = make_float4(w0, w0, w1, w1);
            }
            if (tid < 64) { dbsm[tid] = DB[ph][tid]; pbsm[tid] = PB[ph][tid]; }
            __syncthreads();
        }

        // depthwise 3x3 + bias (R9 verbatim)
        for (int c = cg; c < 64; c += 4) {
            const float* base = xs + c * 180 + drow * 18 + dcol;
            float r[3][4];
#pragma unroll
            for (int dy = 0; dy < 3; dy++) {
                float2 a  = *(const float2*)(base + dy * 18);
                float2 b2 = *(const float2*)(base + dy * 18 + 2);
                r[dy][0] = a.x; r[dy][1] = a.y; r[dy][2] = b2.x; r[dy][3] = b2.y;
            }
            const float* w = fsm + c * 9;
            float s0 = dbsm[c], s1 = s0;
#pragma unroll
            for (int dy = 0; dy < 3; dy++) {
                s0 += w[3*dy] * r[dy][0] + w[3*dy+1] * r[dy][1] + w[3*dy+2] * r[dy][2];
                s1 += w[3*dy] * r[dy][1] + w[3*dy+1] * r[dy][2] + w[3*dy+2] * r[dy][3];
            }
            *(float2*)&dwout[c * 128 + 2 * dp] = make_float2(s0, s1);
        }
        __syncthreads();   // dw done: dwout ready, xs free for next tile

        if (ph != 3) {
            float scale = (ph == 2) ? 2.0f : 1.0f;
#pragma unroll
            for (int i = 0; i < 8; i++) {
                float pbv2 = pbsm[og * 8 + i] * scale;
                acc[i][0] = pk2(pbv2, pbv2);
                acc[i][1] = acc[i][0];
            }
        }

        // prefetch next phase's tile into xs (hidden behind pw)
        if (ph == 2)      load_tile(avg  + (size_t)b * CWH);
        else if (ph == 3) load_tile(mask + (size_t)b * CWH);

        // pointwise 64x64 FFMA2 (R9 verbatim)
        for (int cc = 0; cc < 32; cc++) {
            int c2 = 2 * cc;
            u64t dA0 = *(const u64t*)&dwout[c2 * 128 + 2 * pp0];
            u64t dA1 = *(const u64t*)&dwout[c2 * 128 + 64 + 2 * pp0];
            u64t dB0 = *(const u64t*)&dwout[(c2 + 1) * 128 + 2 * pp0];
            u64t dB1 = *(const u64t*)&dwout[(c2 + 1) * 128 + 64 + 2 * pp0];
#pragma unroll
            for (int i = 0; i < 8; i++) {
                ulonglong2 w2 = *(const ulonglong2*)&pwq[((og * 8 + i) * 32 + cc) * 4];
                acc[i][0] = fma2(w2.x, dA0, acc[i][0]);
                acc[i][1] = fma2(w2.x, dA1, acc[i][1]);
                acc[i][0] = fma2(w2.y, dB0, acc[i][0]);
                acc[i][1] = fma2(w2.y, dB1, acc[i][1]);
            }
        }

        if (ph != 2) {
            float* outp = out_buf(OID[ph]) + (size_t)b * CWH;
            const int q0 = 2 * pp0;
            const int gy0 = ty0 + (q0 >> 4), gx0 = tx0 + (q0 & 15);
            const size_t base0 = (size_t)gy0 * WDIM + gx0;
#pragma unroll
            for (int i = 0; i < 8; i++) {
                int o = og * 8 + i;
                size_t gi0 = (size_t)o * WH + base0;
                size_t gi1 = gi0 + 4 * WDIM;
                *(u64t*)&outp[gi0] = acc[i][0];
                *(u64t*)&outp[gi1] = acc[i][1];
            }
        }
    }
}

// -------------------- QK: R9 body, fine-grained chunks (256 x 256) ------------
#define QSTR 36
#define KSTR 68

__global__ __launch_bounds__(256)
void qk_kernel()
{
    const int b = blockIdx.y;
    const int chunk = blockIdx.x;          // 0..NCHUNK-1
    const int p0 = chunk * 256;            // 256 p-elements = 8 k-tiles
    const int tid = threadIdx.x;
    const int ti = tid >> 4, tj = tid & 15;
    const int i0 = ti * 4, j0 = tj * 4;

    __shared__ __align__(16) float q1s[2][64 * QSTR];
    __shared__ __align__(16) float q2s[2][64 * QSTR];
    __shared__ __align__(16) float ks [2][32 * KSTR];

    const float* qb  = g_q  + (size_t)b * CWH;
    const float* qmb = g_qm + (size_t)b * CWH;
    const float* kb  = g_k  + (size_t)b * CWH;

    auto prefetch = [&](int kt, int s) {
        const int pp2 = p0 + kt * 32;
        for (int e = tid; e < 512; e += 256) {
            int i = e >> 3, u4 = (e & 7) * 4;
            cp16(&q1s[s][i * QSTR + u4], qb  + (size_t)i * WH + pp2 + u4);
            cp16(&q2s[s][i * QSTR + u4], qmb + (size_t)i * WH + pp2 + u4);
        }
        for (int e = tid; e < 512; e += 256) {
            int u = e >> 4, j4 = (e & 15) * 4;
            cp16(&ks[s][u * KSTR + j4], kb + (size_t)(pp2 + u) * 64 + j4);
        }
        cp_commit();
    };

    u64t acc1[4][2] = {};
    u64t acc2[4][2] = {};

    prefetch(0, 0);
    prefetch(1, 1);

    for (int kt = 0; kt < KT_PER_CHUNK; kt++) {
        if (kt == KT_PER_CHUNK - 1) cp_wait<0>(); else cp_wait<1>();
        __syncthreads();
        const int cur = kt & 1;
#pragma unroll 2
        for (int u = 0; u < 32; u++) {
            ulonglong2 bv = *(const ulonglong2*)&ks[cur][u * KSTR + j0];
#pragma unroll
            for (int r = 0; r < 4; r++) {
                float av1 = q1s[cur][(i0 + r) * QSTR + u];
                u64t a1d = pk2(av1, av1);
                acc1[r][0] = fma2(a1d, bv.x, acc1[r][0]);
                acc1[r][1] = fma2(a1d, bv.y, acc1[r][1]);
                float av2 = q2s[cur][(i0 + r) * QSTR + u];
                u64t a2d = pk2(av2, av2);
                acc2[r][0] = fma2(a2d, bv.x, acc2[r][0]);
                acc2[r][1] = fma2(a2d, bv.y, acc2[r][1]);
            }
        }
        __syncthreads();
        if (kt + 2 < KT_PER_CHUNK) prefetch(kt + 2, cur);
    }

    float* P1 = g_part1 + ((size_t)b * NCHUNK + chunk) * 4096;
    float* P2 = g_part2 + ((size_t)b * NCHUNK + chunk) * 4096;
#pragma unroll
    for (int r = 0; r < 4; r++) {
        float a, bb, c, d;
        unpk(acc1[r][0], a, bb); unpk(acc1[r][1], c, d);
        *(float4*)&P1[(i0 + r) * 64 + j0] = make_float4(a, bb, c, d);
        unpk(acc2[r][0], a, bb); unpk(acc2[r][1], c, d);
        *(float4*)&P2[(i0 + r) * 64 + j0] = make_float4(a, bb, c, d);
    }
}

// -------------------- parallel partial reduce (256 chunks) --------------------
__global__ __launch_bounds__(512)
void reduce_kernel()
{
    const int b = blockIdx.y;
    const int e = blockIdx.x * 512 + threadIdx.x;
    const float* P1 = g_part1 + (size_t)b * NCHUNK * 4096;
    const float* P2 = g_part2 + (size_t)b * NCHUNK * 4096;
    float s1 = 0.0f, s2 = 0.0f;
#pragma unroll 8
    for (int ch = 0; ch < NCHUNK; ch++) {
        s1 += P1[(size_t)ch * 4096 + e];
        s2 += P2[(size_t)ch * 4096 + e];
    }
    g_R1[(size_t)b * 4096 + e] = s1 * (1.0f / 256.0f);
    g_R2[(size_t)b * 4096 + e] = s2 * (1.0f / 256.0f);
}

// -------------------- softmax(flat 4096) x2 + M = A1+A2 (verbatim) ----------
__global__ __launch_bounds__(256)
void softmax_kernel()
{
    __shared__ float buf[4096];
    __shared__ float red[256];
    const int b = blockIdx.x;
    const int tid = threadIdx.x;

    for (int m = 0; m < 2; m++) {
        const float* R = (m == 0 ? g_R1 : g_R2) + (size_t)b * 4096;
        __syncthreads();
        float lmax = -1e30f;
        for (int e = tid; e < 4096; e += 256) {
            float s = R[e];
            buf[e] = s;
            lmax = fmaxf(lmax, s);
        }
        red[tid] = lmax; __syncthreads();
        for (int s = 128; s; s >>= 1) {
            if (tid < s) red[tid] = fmaxf(red[tid], red[tid + s]);
            __syncthreads();
        }
        float mx = red[0];
        __syncthreads();

        float lsum = 0.0f;
        for (int e = tid; e < 4096; e += 256) {
            float ev = __expf(buf[e] - mx);
            buf[e] = ev;
            lsum += ev;
        }
        red[tid] = lsum; __syncthreads();
        for (int s = 128; s; s >>= 1) {
            if (tid < s) red[tid] += red[tid + s];
            __syncthreads();
        }
        float inv = 1.0f / red[0];

        for (int e = tid; e < 4096; e += 256) {
            float val = buf[e] * inv;
            float* mp = g_M + (size_t)b * 4096 + e;
            if (m == 0) *mp = val;
            else        *mp += val;
        }
    }
}

// -------------------- out = M @ v_sum + x (verbatim) --------------------
#define OUT_SMEM_FLOATS (8192 + 2 * 8192)

__global__ __launch_bounds__(512)
void out_kernel(const float* __restrict__ x, float* __restrict__ out)
{
    extern __shared__ float osm[];
    float* mq = osm;
    float* vt = osm + 8192;

    const int b  = blockIdx.y;
    const int p0 = blockIdx.x * 512;
    const int tid = threadIdx.x;
    const int pp = tid & 63, og = tid >> 6;

    for (int idx = tid; idx < 2048; idx += 512) {
        int o = idx >> 5, cc = idx & 31;
        float m0 = g_M[(size_t)b * 4096 + o * 64 + 2 * cc];
        float m1 = g_M[(size_t)b * 4096 + o * 64 + 2 * cc + 1];
        ((float4*)mq)[idx] = make_float4(m0, m0, m1, m1);
    }

    const float* vb = g_v + (size_t)b * CWH + p0;

    auto prefetch = [&](int s, int buf) {
        const float* src = vb + s * 128;
        float* dst = vt + buf * 8192;
        for (int e = tid; e < 2048; e += 512) {
            int c = e >> 5, q4 = (e & 31) * 4;
            cp16(&dst[c * 128 + q4], src + (size_t)c * WH + q4);
        }
        cp_commit();
    };

    prefetch(0, 0);
    prefetch(1, 1);

    const float* xb = x + (size_t)b * CWH + p0 + 2 * pp;
    float* ob = out + (size_t)b * CWH + p0 + 2 * pp;

    for (int s = 0; s < 4; s++) {
        if (s == 3) cp_wait<0>(); else cp_wait<1>();
        __syncthreads();
        const float* cvt = vt + (s & 1) * 8192;

        u64t xr[8];
#pragma unroll
        for (int i = 0; i < 8; i++) {
            int o = og * 8 + i;
            xr[i] = *(const u64t*)(xb + (size_t)o * WH + s * 128);
        }

        u64t acc[8] = {};
#pragma unroll 4
        for (int cc = 0; cc < 32; cc++) {
            u64t d0 = *(const u64t*)&cvt[(2 * cc) * 128 + 2 * pp];
            u64t d1 = *(const u64t*)&cvt[(2 * cc + 1) * 128 + 2 * pp];
#pragma unroll
            for (int i = 0; i < 8; i++) {
                ulonglong2 w2 = *(const ulonglong2*)&mq[((og * 8 + i) * 32 + cc) * 4];
                acc[i] = fma2(w2.x, d0, acc[i]);
                acc[i] = fma2(w2.y, d1, acc[i]);
            }
        }

#pragma unroll
        for (int i = 0; i < 8; i++) {
            int o = og * 8 + i;
            *(u64t*)(ob + (size_t)o * WH + s * 128) = add2(acc[i], xr[i]);
        }

        __syncthreads();
        if (s + 2 < 4) prefetch(s + 2, s & 1);
    }
}

// -------------------- launch --------------------
extern "C" void kernel_launch(void* const* d_in, const int* in_sizes, int n_in,
                              void* d_out, int out_size)
{
    const float* x    = (const float*)d_in[0];
    const float* mask = (const float*)d_in[1];
    const float* avg  = (const float*)d_in[2];
    const float* dwq = (const float*)d_in[3];
    const float* dbq = (const float*)d_in[4];
    const float* pwq = (const float*)d_in[5];
    const float* pbq = (const float*)d_in[6];
    const float* dwk = (const float*)d_in[7];
    const float* dbk = (const float*)d_in[8];
    const float* pwk = (const float*)d_in[9];
    const float* pbk = (const float*)d_in[10];
    const float* dwv = (const float*)d_in[11];
    const float* dbv = (const float*)d_in[12];
    const float* pwv = (const float*)d_in[13];
    const float* pbv = (const float*)d_in[14];
    float* out = (float*)d_out;

    const size_t dsc_smem = DSC_SMEM_FLOATS * sizeof(float);
    cudaFuncSetAttribute(dsc5_kernel, cudaFuncAttributeMaxDynamicSharedMemorySize, (int)dsc_smem);
    const size_t out_smem = OUT_SMEM_FLOATS * sizeof(float);
    cudaFuncSetAttribute(out_kernel, cudaFuncAttributeMaxDynamicSharedMemorySize, (int)out_smem);

    dsc5_kernel<<<dim3(WDIM / 16, HDIM / 8, BATCH), 256, dsc_smem>>>(
        x, mask, avg,
        dwq, dbq, pwq, pbq,
        dwk, dbk, pwk, pbk,
        dwv, dbv, pwv, pbv);

    qk_kernel<<<dim3(NCHUNK, BATCH), 256>>>();
    reduce_kernel<<<dim3(8, BATCH), 512>>>();
    softmax_kernel<<<BATCH, 256>>>();
    out_kernel<<<dim3(WH / 512, BATCH), 512, out_smem>>>(x, out);
}